// round 4
// baseline (speedup 1.0000x reference)
#include <cuda_runtime.h>
#include <stdint.h>

// DisplaceChannel: out[b,c,y,x] = inp[b,c, y-off_y[p], x-off_x[p]] (p = c/32),
// zero where source out of [0,64). Offsets are multiples of 32 -> float4
// vectors uniformly valid/invalid, 16B alignment preserved.
//
// Grid = (CH, B); one block per 64x64 plane (1024 float4).
// 256 threads x 4 vectors, loads front-batched (MLP=4).
// NORMAL stores (no __stcs): working set (33.6MB valid reads + 75.5MB out)
// fits in the 126MB L2, so dirty output lines are overwritten in L2 on the
// next graph replay instead of round-tripping to DRAM.

#define CH 288          // 9 * 32
#define H 64
#define W 64
#define W4 16           // float4 per row
#define PLANE4 1024     // H * W4

__global__ __launch_bounds__(256)
void displace_kernel(const float4* __restrict__ in,
                     const int* __restrict__ offsets,
                     float4* __restrict__ out)
{
    const int c = blockIdx.x;          // 0..287
    const int b = blockIdx.y;          // 0..15
    const int p = c >> 5;              // position 0..8

    const int off_x = __ldg(&offsets[2 * p]);
    const int off_y = __ldg(&offsets[2 * p + 1]);

    const long base = ((long)b * CH + c) * PLANE4;
    const float4* __restrict__ src = in + base;
    float4* __restrict__ dst = out + base;

    const int t = threadIdx.x;

    float4 v[4];
#pragma unroll
    for (int j = 0; j < 4; j++) {
        const int vid = t + (j << 8);
        const int x4 = vid & (W4 - 1);
        const int y  = vid >> 4;
        const int sy = y - off_y;
        const int sx = (x4 << 2) - off_x;
        v[j] = make_float4(0.f, 0.f, 0.f, 0.f);
        if ((unsigned)sy < H && (unsigned)sx < W) {
            v[j] = __ldg(&src[(sy << 4) + (sx >> 2)]);
        }
    }
#pragma unroll
    for (int j = 0; j < 4; j++) {
        dst[t + (j << 8)] = v[j];      // evict_normal: let output live in L2
    }
}

extern "C" void kernel_launch(void* const* d_in, const int* in_sizes, int n_in,
                              void* d_out, int out_size)
{
    const float4* in = (const float4*)d_in[0];
    const int* offsets = (const int*)d_in[1];
    float4* out = (float4*)d_out;

    dim3 grid(CH, 16);   // (channels, batch)
    displace_kernel<<<grid, 256>>>(in, offsets, out);
}

// round 5
// speedup vs baseline: 1.1175x; 1.1175x over previous
#include <cuda_runtime.h>
#include <stdint.h>

// DisplaceChannel: out[b,c,y,x] = inp[b,c, y-off_y[p], x-off_x[p]] (p = c/32),
// zero where source out of [0,64). Offsets are multiples of 32 -> float4
// vectors uniformly valid/invalid, 16B alignment preserved.
//
// Single-wave launch: grid (72,16) = 1152 blocks <= 148 SMs * 8 blocks,
// 256 threads (8 warps), regs kept <= 32 so 64 warps/SM fit. Each block
// handles 4 consecutive channels (same position group since 4 | 32).
// Per channel: 4 front-batched float4 loads (MLP=4) then 4 __stcs stores
// (output streamed past L2 so the input stays L2-resident across replays).

#define CH 288          // 9 * 32
#define H 64
#define W 64
#define W4 16           // float4 per row
#define PLANE4 1024     // H * W4

__global__ __launch_bounds__(256, 8)
void displace_kernel(const float4* __restrict__ in,
                     const int* __restrict__ offsets,
                     float4* __restrict__ out)
{
    const int c0 = blockIdx.x << 2;    // first of 4 channels, 0..284
    const int b  = blockIdx.y;         // 0..15
    const int p  = c0 >> 5;            // position 0..8 (same for all 4 channels)

    const int off_x = __ldg(&offsets[2 * p]);
    const int off_y = __ldg(&offsets[2 * p + 1]);

    const int t = threadIdx.x;

    // Per-thread source geometry is identical across the 4 channels:
    // precompute validity and within-plane source offset for each of the
    // 4 vector slots this thread owns.
    int srcoff[4];
    bool valid[4];
#pragma unroll
    for (int j = 0; j < 4; j++) {
        const int vid = t + (j << 8);          // 0..1023
        const int x4  = vid & (W4 - 1);
        const int y   = vid >> 4;
        const int sy  = y - off_y;
        const int sx  = (x4 << 2) - off_x;
        valid[j]  = ((unsigned)sy < H) & ((unsigned)sx < W);
        srcoff[j] = (sy << 4) + (sx >> 2);
    }

    long base = ((long)b * CH + c0) * PLANE4;

#pragma unroll
    for (int k = 0; k < 4; k++) {
        const float4* __restrict__ src = in + base;
        float4* __restrict__ dst = out + base;

        float4 v[4];
#pragma unroll
        for (int j = 0; j < 4; j++) {
            v[j] = make_float4(0.f, 0.f, 0.f, 0.f);
            if (valid[j]) {
                v[j] = __ldg(&src[srcoff[j]]);
            }
        }
#pragma unroll
        for (int j = 0; j < 4; j++) {
            __stcs(&dst[t + (j << 8)], v[j]);  // stream output past L2
        }
        base += PLANE4;
    }
}

extern "C" void kernel_launch(void* const* d_in, const int* in_sizes, int n_in,
                              void* d_out, int out_size)
{
    const float4* in = (const float4*)d_in[0];
    const int* offsets = (const int*)d_in[1];
    float4* out = (float4*)d_out;

    dim3 grid(CH / 4, 16);   // (channel quads, batch) = 1152 blocks
    displace_kernel<<<grid, 256>>>(in, offsets, out);
}